// round 16
// baseline (speedup 1.0000x reference)
#include <cuda_runtime.h>
#include <cuda_fp16.h>
#include <cstdint>
#include <math.h>

#define T_TOKENS 8192
#define H_DIM    1024
#define F_DIM    4096
#define E_NUM    8
#define NPAIR    (T_TOKENS * 2)
#define WEL      (E_NUM * F_DIM * H_DIM)
#define MT_MAX   (NPAIR / 128 + E_NUM - 1)   // 135 (128-row tiles, down)
#define MT256    (NPAIR / 256 + E_NUM)       // 72  (256-row tiles, gateup)

// ---------------- scratch (device globals) ----------------
__device__ int    g_ke[NPAIR];
__device__ float  g_kw[NPAIR];
__device__ int    g_off[E_NUM + 1];
__device__ int    g_toff[E_NUM + 1];          // 128-row tile prefix (down)
__device__ int    g_toff2[E_NUM + 1];         // 256-row tile prefix (gateup)
__device__ int    g_stok[NPAIR];
__device__ float  g_sw[NPAIR + 256];          // padded (tile overread safety)
__device__ __half g_axh[(size_t)(NPAIR + 256) * H_DIM];   // padded
__device__ __half g_hidh[(size_t)NPAIR * F_DIM];
__device__ __half g_gwh[WEL];
__device__ __half g_uwh[WEL];
__device__ __half g_dwh[WEL];

// ---------------- helpers ----------------
__device__ __forceinline__ uint32_t smem_u32(const void* p) {
    uint32_t a;
    asm("{ .reg .u64 t; cvta.to.shared.u64 t, %1; cvt.u32.u64 %0, t; }" : "=r"(a) : "l"(p));
    return a;
}
__device__ __forceinline__ void mma_f16(float* c, const unsigned* a, const unsigned* b) {
    asm volatile(
        "mma.sync.aligned.m16n8k16.row.col.f32.f16.f16.f32 "
        "{%0,%1,%2,%3}, {%4,%5,%6,%7}, {%8,%9}, {%0,%1,%2,%3};\n"
        : "+f"(c[0]), "+f"(c[1]), "+f"(c[2]), "+f"(c[3])
        : "r"(a[0]), "r"(a[1]), "r"(a[2]), "r"(a[3]), "r"(b[0]), "r"(b[1]));
}
__device__ __forceinline__ void ldsm_x4(unsigned& r0, unsigned& r1, unsigned& r2, unsigned& r3,
                                        uint32_t addr) {
    asm volatile("ldmatrix.sync.aligned.m8n8.x4.shared.b16 {%0,%1,%2,%3}, [%4];"
                 : "=r"(r0), "=r"(r1), "=r"(r2), "=r"(r3) : "r"(addr));
}
__device__ __forceinline__ void cp16(uint32_t dst, const void* src) {
    asm volatile("cp.async.cg.shared.global [%0], [%1], 16;" :: "r"(dst), "l"(src) : "memory");
}
#define CP_COMMIT() asm volatile("cp.async.commit_group;" ::: "memory")
#define CP_WAIT0()  asm volatile("cp.async.wait_group 0;" ::: "memory")
#define CP_WAIT1()  asm volatile("cp.async.wait_group 1;" ::: "memory")

#define PADH 72
// gateup (BM=256): A[256*72] @0 | Bg[64*72] @18432 | Bu[64*72] @23040
#define G2_BG (256 * PADH)
#define G2_BU (G2_BG + 64 * PADH)
#define G2_STGH ((256 + 64 + 64) * PADH)   // 27648 halves / stage
#define G2_SMEM (2 * G2_STGH * 2)          // 110592 B
// down (BM=128, R11): A[128*72] | B[128*72], 3 stages
#define DN_BB (128 * PADH)
#define DN_STGH ((128 + 128) * PADH)
#define NSTG 3
#define DN_SMEM (NSTG * DN_STGH * 2)       // 110592 B

// ---------------- 1) router ----------------
__global__ void router_kernel(const float* __restrict__ x, const float* __restrict__ rw) {
    int warp = threadIdx.x >> 5;
    int lane = threadIdx.x & 31;
    int t = blockIdx.x * 8 + warp;
    const float4* xr = (const float4*)(x + (size_t)t * H_DIM);
    float acc[E_NUM];
#pragma unroll
    for (int e = 0; e < E_NUM; e++) acc[e] = 0.f;
#pragma unroll
    for (int it = 0; it < H_DIM / 128; it++) {
        float4 xv = xr[it * 32 + lane];
#pragma unroll
        for (int e = 0; e < E_NUM; e++) {
            float4 wv = ((const float4*)(rw + (size_t)e * H_DIM))[it * 32 + lane];
            acc[e] += xv.x * wv.x + xv.y * wv.y + xv.z * wv.z + xv.w * wv.w;
        }
    }
#pragma unroll
    for (int e = 0; e < E_NUM; e++)
#pragma unroll
        for (int o = 16; o > 0; o >>= 1)
            acc[e] += __shfl_xor_sync(0xffffffffu, acc[e], o);
    if (lane == 0) {
        float mx = acc[0];
#pragma unroll
        for (int e = 1; e < E_NUM; e++) mx = fmaxf(mx, acc[e]);
        float p[E_NUM], s = 0.f;
#pragma unroll
        for (int e = 0; e < E_NUM; e++) { p[e] = expf(acc[e] - mx); s += p[e]; }
        float inv = 1.f / s;
        int i1 = 0;
#pragma unroll
        for (int e = 1; e < E_NUM; e++) if (acc[e] > acc[i1]) i1 = e;
        int i2 = (i1 == 0) ? 1 : 0;
#pragma unroll
        for (int e = 0; e < E_NUM; e++) {
            if (e == i1) continue;
            if (acc[e] > acc[i2]) i2 = e;
        }
        g_ke[t * 2]     = i1;  g_kw[t * 2]     = p[i1] * inv;
        g_ke[t * 2 + 1] = i2;  g_kw[t * 2 + 1] = p[i2] * inv;
    }
}

// ---------------- 2) build buckets + tile prefixes ----------------
__global__ void build_kernel() {
    __shared__ int cnt[E_NUM], fill[E_NUM], off_s[E_NUM + 1];
    if (threadIdx.x < E_NUM) { cnt[threadIdx.x] = 0; fill[threadIdx.x] = 0; }
    __syncthreads();
    for (int i = threadIdx.x; i < NPAIR; i += blockDim.x)
        atomicAdd(&cnt[g_ke[i]], 1);
    __syncthreads();
    if (threadIdx.x == 0) {
        int s = 0, ts = 0, ts2 = 0;
        for (int e = 0; e < E_NUM; e++) {
            off_s[e] = s;
            g_off[e] = s;
            g_toff[e] = ts;
            g_toff2[e] = ts2;
            s += cnt[e];
            ts += (cnt[e] + 127) / 128;
            ts2 += (cnt[e] + 255) / 256;
        }
        off_s[E_NUM] = s;
        g_off[E_NUM] = s;
        g_toff[E_NUM] = ts;
        g_toff2[E_NUM] = ts2;
    }
    __syncthreads();
    for (int i = threadIdx.x; i < NPAIR; i += blockDim.x) {
        int e = g_ke[i];
        int pos = off_s[e] + atomicAdd(&fill[e], 1);
        g_stok[pos] = i >> 1;
        g_sw[pos] = g_kw[i];
    }
}

// ---------------- 3) prep: weights->fp16, gather A, zero out ----------------
__global__ void prep_kernel(const float* __restrict__ x,
                            const float* __restrict__ gw,
                            const float* __restrict__ uw,
                            const float* __restrict__ dw,
                            __half* __restrict__ gwh,
                            __half* __restrict__ uwh,
                            __half* __restrict__ dwh,
                            float* __restrict__ out, int n16) {
    if (blockIdx.y < 3) {
        const float* src = (blockIdx.y == 0) ? gw : (blockIdx.y == 1) ? uw : dw;
        __half* dst = (blockIdx.y == 0) ? gwh : (blockIdx.y == 1) ? uwh : dwh;
        int i = blockIdx.x * blockDim.x + threadIdx.x;
        int stride = gridDim.x * blockDim.x;
        for (; i < n16; i += stride) {
            const float4* s = (const float4*)(src + (size_t)i * 16);
            float4 v0 = s[0], v1 = s[1], v2 = s[2], v3 = s[3];
            __half o[16];
            o[0]  = __float2half_rn(v0.x); o[1]  = __float2half_rn(v0.y);
            o[2]  = __float2half_rn(v0.z); o[3]  = __float2half_rn(v0.w);
            o[4]  = __float2half_rn(v1.x); o[5]  = __float2half_rn(v1.y);
            o[6]  = __float2half_rn(v1.z); o[7]  = __float2half_rn(v1.w);
            o[8]  = __float2half_rn(v2.x); o[9]  = __float2half_rn(v2.y);
            o[10] = __float2half_rn(v2.z); o[11] = __float2half_rn(v2.w);
            o[12] = __float2half_rn(v3.x); o[13] = __float2half_rn(v3.y);
            o[14] = __float2half_rn(v3.z); o[15] = __float2half_rn(v3.w);
            uint4* d = (uint4*)(dst + (size_t)i * 16);
            d[0] = ((const uint4*)o)[0];
            d[1] = ((const uint4*)o)[1];
        }
    } else if (blockIdx.y == 3) {
        int row = blockIdx.x * 4 + (threadIdx.x >> 6);
        int grp = threadIdx.x & 63;
        int tok = g_stok[row];
        const float4* s = (const float4*)(x + (size_t)tok * H_DIM + grp * 16);
        float4 v0 = s[0], v1 = s[1], v2 = s[2], v3 = s[3];
        __half o[16];
        o[0]  = __float2half_rn(v0.x); o[1]  = __float2half_rn(v0.y);
        o[2]  = __float2half_rn(v0.z); o[3]  = __float2half_rn(v0.w);
        o[4]  = __float2half_rn(v1.x); o[5]  = __float2half_rn(v1.y);
        o[6]  = __float2half_rn(v1.z); o[7]  = __float2half_rn(v1.w);
        o[8]  = __float2half_rn(v2.x); o[9]  = __float2half_rn(v2.y);
        o[10] = __float2half_rn(v2.z); o[11] = __float2half_rn(v2.w);
        o[12] = __float2half_rn(v3.x); o[13] = __float2half_rn(v3.y);
        o[14] = __float2half_rn(v3.z); o[15] = __float2half_rn(v3.w);
        uint4* d = (uint4*)(g_axh + (size_t)row * H_DIM + grp * 16);
        d[0] = ((const uint4*)o)[0];
        d[1] = ((const uint4*)o)[1];
    } else {
        int i = blockIdx.x * blockDim.x + threadIdx.x;
        float4 z = make_float4(0.f, 0.f, 0.f, 0.f);
        float4* po = (float4*)out;
        po[i] = z;
        po[i + 1048576] = z;
    }
}

// ---------------- 4) gate+up GEMM: BM=256, 8 warps (4Mx2N), warp tile 64x32 per matrix ----------------
__global__ __launch_bounds__(256, 2)
void gateup_mm(const __half* __restrict__ gw, const __half* __restrict__ uw)
{
    const int wi = blockIdx.x;
    const int mtile = wi >> 6;
    if (mtile >= g_toff2[E_NUM]) return;
    int e = 0;
#pragma unroll
    for (int k = 1; k < E_NUM; k++) if (mtile >= g_toff2[k]) e = k;
    const int off0 = g_off[e];
    const int nrows = g_off[e + 1] - off0;
    const int m0 = (mtile - g_toff2[e]) * 256;
    const int n0 = (wi & 63) * 64;
    const int tid = threadIdx.x;
    const int wid = tid >> 5, lane = tid & 31;
    const int warpM = wid & 3, warpN = wid >> 2;   // 4 x 2
    const int g = lane >> 2, t = lane & 3;

    extern __shared__ __half smh[];
    __shared__ float ws[256];
    const uint32_t sbase = smem_u32(smh);

    {
        int r = m0 + tid;
        ws[tid] = (r < nrows) ? g_sw[off0 + r] : 0.f;
    }

    // A fill: 256 rows x 8 cols(16B); thread covers rows (tid>>3)+32i, col tid&7 (affine, padded array)
    const __half* aSrc0 = g_axh + (size_t)(off0 + m0 + (tid >> 3)) * H_DIM + (tid & 7) * 8;
    const uint32_t aDst0 = sbase + ((tid >> 3) * PADH + (tid & 7) * 8) * 2;
    const size_t   dAs = (size_t)32 * H_DIM;       // +32 rows in gmem
    const uint32_t dAd = 32 * PADH * 2;            // +32 rows in smem
    // B fill: 64 rows x 8 cols each for g and u; thread covers rows (tid>>3)+32i (i=0,1)
    const __half* gSrc0 = gw + (size_t)e * F_DIM * H_DIM
                        + (size_t)(n0 + (tid >> 3)) * H_DIM + (tid & 7) * 8;
    const ptrdiff_t du = uw - gw;
    const uint32_t bDst0 = sbase + ((tid >> 3) * PADH + (tid & 7) * 8) * 2;

    uint32_t aoff[4];
#pragma unroll
    for (int mt = 0; mt < 4; mt++)
        aoff[mt] = (uint32_t)(((warpM * 64 + mt * 16 + (lane & 15)) * PADH
                               + ((lane >> 4) & 1) * 8) * 2);
    const int brow = (lane & 7) + ((lane >> 4) & 1) * 8;
    const int bks  = ((lane >> 3) & 1) * 8;
    uint32_t boff[2];
#pragma unroll
    for (int p = 0; p < 2; p++)
        boff[p] = (uint32_t)(((warpN * 32 + p * 16 + brow) * PADH + bks) * 2);

    float accg[4][4][4], accu[4][4][4];
#pragma unroll
    for (int mt = 0; mt < 4; mt++)
#pragma unroll
        for (int nt = 0; nt < 4; nt++)
#pragma unroll
            for (int i = 0; i < 4; i++) { accg[mt][nt][i] = 0.f; accu[mt][nt][i] = 0.f; }

    const int NK = H_DIM / 64;  // 16
    // prologue: fill stage 0
#pragma unroll
    for (int i = 0; i < 8; i++) cp16(aDst0 + i * dAd, aSrc0 + i * dAs);
#pragma unroll
    for (int i = 0; i < 2; i++) {
        cp16(bDst0 + G2_BG * 2 + i * dAd, gSrc0 + i * dAs);
        cp16(bDst0 + G2_BU * 2 + i * dAd, gSrc0 + du + i * dAs);
    }
    CP_COMMIT();

    int s = 0;
    for (int kb = 0; kb < NK; kb++) {
        CP_WAIT0();        // stage s (kb) landed
        __syncthreads();   // all warps finished reading stage s^1 (kb-1)
        if (kb + 1 < NK) {
            const uint32_t so = (uint32_t)((s ^ 1) * G2_STGH * 2);
            const int ko = (kb + 1) * 64;
#pragma unroll
            for (int i = 0; i < 8; i++) cp16(aDst0 + so + i * dAd, aSrc0 + ko + i * dAs);
#pragma unroll
            for (int i = 0; i < 2; i++) {
                cp16(bDst0 + so + G2_BG * 2 + i * dAd, gSrc0 + ko + i * dAs);
                cp16(bDst0 + so + G2_BU * 2 + i * dAd, gSrc0 + ko + du + i * dAs);
            }
            CP_COMMIT();
        }
        const uint32_t sA = sbase + (uint32_t)(s * G2_STGH * 2);
#pragma unroll
        for (int ks = 0; ks < 4; ks++) {
            const uint32_t kofs = (uint32_t)(ks * 32);
            unsigned a[4][4], bg[2][4], bu[2][4];
#pragma unroll
            for (int mt = 0; mt < 4; mt++)
                ldsm_x4(a[mt][0], a[mt][1], a[mt][2], a[mt][3], sA + aoff[mt] + kofs);
#pragma unroll
            for (int p = 0; p < 2; p++) {
                ldsm_x4(bg[p][0], bg[p][1], bg[p][2], bg[p][3], sA + G2_BG * 2 + boff[p] + kofs);
                ldsm_x4(bu[p][0], bu[p][1], bu[p][2], bu[p][3], sA + G2_BU * 2 + boff[p] + kofs);
            }
#pragma unroll
            for (int mt = 0; mt < 4; mt++)
#pragma unroll
                for (int p = 0; p < 2; p++) {
                    mma_f16(accg[mt][p * 2 + 0], a[mt], &bg[p][0]);
                    mma_f16(accg[mt][p * 2 + 1], a[mt], &bg[p][2]);
                    mma_f16(accu[mt][p * 2 + 0], a[mt], &bu[p][0]);
                    mma_f16(accu[mt][p * 2 + 1], a[mt], &bu[p][2]);
                }
        }
        s ^= 1;
    }

    // epilogue: hid = fp16( w * silu(g) * u )
#pragma unroll
    for (int mt = 0; mt < 4; mt++) {
#pragma unroll
        for (int nt = 0; nt < 4; nt++) {
            const int col = n0 + warpN * 32 + nt * 8 + t * 2;
#pragma unroll
            for (int h = 0; h < 2; h++) {
                const int row = warpM * 64 + mt * 16 + g + h * 8;
                if (m0 + row < nrows) {
                    float w  = ws[row];
                    float g0 = accg[mt][nt][h * 2 + 0], g1 = accg[mt][nt][h * 2 + 1];
                    float u0 = accu[mt][nt][h * 2 + 0], u1 = accu[mt][nt][h * 2 + 1];
                    float h0 = w * u0 * (g0 / (1.f + __expf(-g0)));
                    float h1 = w * u1 * (g1 / (1.f + __expf(-g1)));
                    *(__half2*)(g_hidh + (size_t)(off0 + m0 + row) * F_DIM + col) =
                        __floats2half2_rn(h0, h1);
                }
            }
        }
    }
}

// ---------------- 5) down GEMM (R11 config: BM=128, 3-stage, fused combine) ----------------
__global__ __launch_bounds__(256, 2)
void down_mm(float* __restrict__ out)
{
    const int wi = blockIdx.x;
    const int mtile = wi >> 3;
    if (mtile >= g_toff[E_NUM]) return;
    int e = 0;
#pragma unroll
    for (int k = 1; k < E_NUM; k++) if (mtile >= g_toff[k]) e = k;
    const int off0 = g_off[e];
    const int nrows = g_off[e + 1] - off0;
    const int m0 = (mtile - g_toff[e]) * 128;
    const int n0 = (wi & 7) * 128;
    const int tid = threadIdx.x;
    const int wid = tid >> 5, lane = tid & 31;
    const int warpM = wid & 3, warpN = wid >> 2;
    const int g = lane >> 2, t = lane & 3;

    extern __shared__ __half smh[];
    const uint32_t sbase = smem_u32(smh);

    const __half* aSrc[4]; uint32_t aDst[4];
    const __half* bSrc[4]; uint32_t bDst[4];
#pragma unroll
    for (int i = 0; i < 4; i++) {
        int c = tid + 256 * i;
        int row = c >> 3, col = c & 7;
        int r = m0 + row; if (r > nrows - 1) r = nrows - 1;
        aSrc[i] = g_hidh + (size_t)(off0 + r) * F_DIM + col * 8;
        aDst[i] = sbase + (row * PADH + col * 8) * 2;
        bSrc[i] = g_dwh + (size_t)e * H_DIM * F_DIM + (size_t)(n0 + row) * F_DIM + col * 8;
        bDst[i] = sbase + ((DN_BB + row * PADH + col * 8)) * 2;
    }

    uint32_t aoff[2];
#pragma unroll
    for (int mt = 0; mt < 2; mt++)
        aoff[mt] = (uint32_t)(((warpM * 32 + mt * 16 + (lane & 15)) * PADH
                               + ((lane >> 4) & 1) * 8) * 2);
    const int brow = (lane & 7) + ((lane >> 4) & 1) * 8;
    const int bks  = ((lane >> 3) & 1) * 8;
    uint32_t boff[4];
#pragma unroll
    for (int p = 0; p < 4; p++)
        boff[p] = (uint32_t)(((warpN * 64 + p * 16 + brow) * PADH + bks) * 2);

    float acc[2][8][4];
#pragma unroll
    for (int mt = 0; mt < 2; mt++)
#pragma unroll
        for (int nt = 0; nt < 8; nt++)
#pragma unroll
            for (int i = 0; i < 4; i++) acc[mt][nt][i] = 0.f;

    const int NK = F_DIM / 64;  // 64
#pragma unroll
    for (int pk = 0; pk < 2; pk++) {
        const uint32_t so = (uint32_t)(pk * DN_STGH * 2);
        const int ko = pk * 64;
#pragma unroll
        for (int i = 0; i < 4; i++) {
            cp16(aDst[i] + so, aSrc[i] + ko);
            cp16(bDst[i] + so, bSrc[i] + ko);
        }
        CP_COMMIT();
    }

    int s = 0;
    for (int kb = 0; kb < NK; kb++) {
        if (kb + 1 < NK) CP_WAIT1(); else CP_WAIT0();
        __syncthreads();
        if (kb + 2 < NK) {
            const int s2 = (s + 2 >= NSTG) ? (s + 2 - NSTG) : (s + 2);
            const uint32_t so = (uint32_t)(s2 * DN_STGH * 2);
            const int ko = (kb + 2) * 64;
#pragma unroll
            for (int i = 0; i < 4; i++) {
                cp16(aDst[i] + so, aSrc[i] + ko);
                cp16(bDst[i] + so, bSrc[i] + ko);
            }
            CP_COMMIT();
        }
        const uint32_t sA = sbase + (uint32_t)(s * DN_STGH * 2);
#pragma unroll
        for (int ks = 0; ks < 4; ks++) {
            const uint32_t kofs = (uint32_t)(ks * 32);
            unsigned a[2][4], b[4][4];
#pragma unroll
            for (int mt = 0; mt < 2; mt++)
                ldsm_x4(a[mt][0], a[mt][1], a[mt][2], a[mt][3], sA + aoff[mt] + kofs);
#pragma unroll
            for (int p = 0; p < 4; p++)
                ldsm_x4(b[p][0], b[p][1], b[p][2], b[p][3], sA + DN_BB * 2 + boff[p] + kofs);
#pragma unroll
            for (int mt = 0; mt < 2; mt++)
#pragma unroll
                for (int p = 0; p < 4; p++) {
                    mma_f16(acc[mt][p * 2 + 0], a[mt], &b[p][0]);
                    mma_f16(acc[mt][p * 2 + 1], a[mt], &b[p][2]);
                }
        }
        s = (s + 1 >= NSTG) ? 0 : (s + 1);
    }

    // epilogue: atomicAdd into output (exactly 2 contributions per element -> deterministic)
#pragma unroll
    for (int mt = 0; mt < 2; mt++) {
#pragma unroll
        for (int h = 0; h < 2; h++) {
            const int row = warpM * 32 + mt * 16 + g + h * 8;
            if (m0 + row < nrows) {
                const int tok = g_stok[off0 + m0 + row];
                float* po = out + (size_t)tok * H_DIM;
#pragma unroll
                for (int nt = 0; nt < 8; nt++) {
                    const int col = n0 + warpN * 64 + nt * 8 + t * 2;
                    atomicAdd(po + col,     acc[mt][nt][h * 2 + 0]);
                    atomicAdd(po + col + 1, acc[mt][nt][h * 2 + 1]);
                }
            }
        }
    }
}

// ---------------- launch ----------------
extern "C" void kernel_launch(void* const* d_in, const int* in_sizes, int n_in,
                              void* d_out, int out_size) {
    (void)in_sizes; (void)n_in; (void)out_size;
    const float* x  = (const float*)d_in[0];
    const float* rw = (const float*)d_in[1];
    const float* gw = (const float*)d_in[2];
    const float* uw = (const float*)d_in[3];
    const float* dw = (const float*)d_in[4];
    float* out = (float*)d_out;

    cudaFuncSetAttribute(gateup_mm, cudaFuncAttributeMaxDynamicSharedMemorySize, G2_SMEM);
    cudaFuncSetAttribute(down_mm,   cudaFuncAttributeMaxDynamicSharedMemorySize, DN_SMEM);

    __half* gwh; __half* uwh; __half* dwh;
    cudaGetSymbolAddress((void**)&gwh, g_gwh);
    cudaGetSymbolAddress((void**)&uwh, g_uwh);
    cudaGetSymbolAddress((void**)&dwh, g_dwh);

    const int n16 = WEL / 16;

    // launch order: gateup_mm is the 4th launch (= ncu's profiled slot)
    router_kernel<<<T_TOKENS / 8, 256>>>(x, rw);                                   // 1
    build_kernel<<<1, 256>>>();                                                    // 2
    prep_kernel<<<dim3(4096, 5), 256>>>(x, gw, uw, dw, gwh, uwh, dwh, out, n16);   // 3
    gateup_mm<<<MT256 * 64, 256, G2_SMEM>>>(gwh, uwh);                             // 4 <- profiled
    down_mm<<<MT_MAX * 8, 256, DN_SMEM>>>(out);                                    // 5
}

// round 17
// speedup vs baseline: 2.1701x; 2.1701x over previous
#include <cuda_runtime.h>
#include <cuda_fp16.h>
#include <cstdint>
#include <math.h>

#define T_TOKENS 8192
#define H_DIM    1024
#define F_DIM    4096
#define E_NUM    8
#define NPAIR    (T_TOKENS * 2)
#define WEL      (E_NUM * F_DIM * H_DIM)
#define MT_MAX   (NPAIR / 128 + E_NUM - 1)   // 135

// ---------------- scratch (device globals) ----------------
__device__ int    g_ke[NPAIR];
__device__ float  g_kw[NPAIR];
__device__ int    g_off[E_NUM + 1];
__device__ int    g_toff[E_NUM + 1];
__device__ int    g_stok[NPAIR];
__device__ float  g_sw[NPAIR];
__device__ __half g_axh[(size_t)NPAIR * H_DIM];
__device__ __half g_hidh[(size_t)NPAIR * F_DIM];
__device__ __half g_gwh[WEL];
__device__ __half g_uwh[WEL];
__device__ __half g_dwh[WEL];

// ---------------- helpers ----------------
__device__ __forceinline__ uint32_t smem_u32(const void* p) {
    uint32_t a;
    asm("{ .reg .u64 t; cvta.to.shared.u64 t, %1; cvt.u32.u64 %0, t; }" : "=r"(a) : "l"(p));
    return a;
}
__device__ __forceinline__ void mma_f16(float* c, const unsigned* a, const unsigned* b) {
    asm volatile(
        "mma.sync.aligned.m16n8k16.row.col.f32.f16.f16.f32 "
        "{%0,%1,%2,%3}, {%4,%5,%6,%7}, {%8,%9}, {%0,%1,%2,%3};\n"
        : "+f"(c[0]), "+f"(c[1]), "+f"(c[2]), "+f"(c[3])
        : "r"(a[0]), "r"(a[1]), "r"(a[2]), "r"(a[3]), "r"(b[0]), "r"(b[1]));
}
__device__ __forceinline__ void ldsm_x4(unsigned& r0, unsigned& r1, unsigned& r2, unsigned& r3,
                                        uint32_t addr) {
    asm volatile("ldmatrix.sync.aligned.m8n8.x4.shared.b16 {%0,%1,%2,%3}, [%4];"
                 : "=r"(r0), "=r"(r1), "=r"(r2), "=r"(r3) : "r"(addr));
}
__device__ __forceinline__ void cp16(uint32_t dst, const void* src) {
    asm volatile("cp.async.cg.shared.global [%0], [%1], 16;" :: "r"(dst), "l"(src) : "memory");
}
#define CP_COMMIT() asm volatile("cp.async.commit_group;" ::: "memory")
#define CP_WAIT0()  asm volatile("cp.async.wait_group 0;" ::: "memory")
#define CP_WAIT1()  asm volatile("cp.async.wait_group 1;" ::: "memory")

#define PADH 72
#define GU_BG (128 * PADH)
#define GU_BU (GU_BG + 64 * PADH)
#define GU_STGH ((128 + 64 + 64) * PADH)
#define DN_BB (128 * PADH)
#define DN_STGH ((128 + 128) * PADH)
#define NSTG 3
#define GU_SMEM (NSTG * GU_STGH * 2)
#define DN_SMEM (NSTG * DN_STGH * 2)

// ---------------- 1) prep: weights->fp16 | zero out | router (all independent) ----------------
// blockIdx.y: 0..2 = weight tensors, 3 = zero output, 4 = router
__global__ void prep_kernel(const float* __restrict__ x,
                            const float* __restrict__ rw,
                            const float* __restrict__ gw,
                            const float* __restrict__ uw,
                            const float* __restrict__ dw,
                            __half* __restrict__ gwh,
                            __half* __restrict__ uwh,
                            __half* __restrict__ dwh,
                            float* __restrict__ out, int n16) {
    if (blockIdx.y < 3) {
        const float* src = (blockIdx.y == 0) ? gw : (blockIdx.y == 1) ? uw : dw;
        __half* dst = (blockIdx.y == 0) ? gwh : (blockIdx.y == 1) ? uwh : dwh;
        int i = blockIdx.x * blockDim.x + threadIdx.x;
        int stride = gridDim.x * blockDim.x;
        for (; i < n16; i += stride) {
            const float4* s = (const float4*)(src + (size_t)i * 16);
            float4 v0 = s[0], v1 = s[1], v2 = s[2], v3 = s[3];
            __half o[16];
            o[0]  = __float2half_rn(v0.x); o[1]  = __float2half_rn(v0.y);
            o[2]  = __float2half_rn(v0.z); o[3]  = __float2half_rn(v0.w);
            o[4]  = __float2half_rn(v1.x); o[5]  = __float2half_rn(v1.y);
            o[6]  = __float2half_rn(v1.z); o[7]  = __float2half_rn(v1.w);
            o[8]  = __float2half_rn(v2.x); o[9]  = __float2half_rn(v2.y);
            o[10] = __float2half_rn(v2.z); o[11] = __float2half_rn(v2.w);
            o[12] = __float2half_rn(v3.x); o[13] = __float2half_rn(v3.y);
            o[14] = __float2half_rn(v3.z); o[15] = __float2half_rn(v3.w);
            uint4* d = (uint4*)(dst + (size_t)i * 16);
            d[0] = ((const uint4*)o)[0];
            d[1] = ((const uint4*)o)[1];
        }
    } else if (blockIdx.y == 3) {
        int i = blockIdx.x * blockDim.x + threadIdx.x;
        float4 z = make_float4(0.f, 0.f, 0.f, 0.f);
        float4* po = (float4*)out;
        po[i] = z;
        po[i + 1048576] = z;
    } else {
        if (blockIdx.x >= T_TOKENS / 8) return;
        int warp = threadIdx.x >> 5;
        int lane = threadIdx.x & 31;
        int t = blockIdx.x * 8 + warp;
        const float4* xr = (const float4*)(x + (size_t)t * H_DIM);
        float acc[E_NUM];
#pragma unroll
        for (int e = 0; e < E_NUM; e++) acc[e] = 0.f;
#pragma unroll
        for (int it = 0; it < H_DIM / 128; it++) {
            float4 xv = xr[it * 32 + lane];
#pragma unroll
            for (int e = 0; e < E_NUM; e++) {
                float4 wv = ((const float4*)(rw + (size_t)e * H_DIM))[it * 32 + lane];
                acc[e] += xv.x * wv.x + xv.y * wv.y + xv.z * wv.z + xv.w * wv.w;
            }
        }
#pragma unroll
        for (int e = 0; e < E_NUM; e++)
#pragma unroll
            for (int o = 16; o > 0; o >>= 1)
                acc[e] += __shfl_xor_sync(0xffffffffu, acc[e], o);
        if (lane == 0) {
            float mx = acc[0];
#pragma unroll
            for (int e = 1; e < E_NUM; e++) mx = fmaxf(mx, acc[e]);
            float p[E_NUM], s = 0.f;
#pragma unroll
            for (int e = 0; e < E_NUM; e++) { p[e] = expf(acc[e] - mx); s += p[e]; }
            float inv = 1.f / s;
            int i1 = 0;
#pragma unroll
            for (int e = 1; e < E_NUM; e++) if (acc[e] > acc[i1]) i1 = e;
            int i2 = (i1 == 0) ? 1 : 0;
#pragma unroll
            for (int e = 0; e < E_NUM; e++) {
                if (e == i1) continue;
                if (acc[e] > acc[i2]) i2 = e;
            }
            g_ke[t * 2]     = i1;  g_kw[t * 2]     = p[i1] * inv;
            g_ke[t * 2 + 1] = i2;  g_kw[t * 2 + 1] = p[i2] * inv;
        }
    }
}

// ---------------- 2) build buckets + tile prefix ----------------
__global__ void build_kernel() {
    __shared__ int cnt[E_NUM], fill[E_NUM], off_s[E_NUM + 1];
    if (threadIdx.x < E_NUM) { cnt[threadIdx.x] = 0; fill[threadIdx.x] = 0; }
    __syncthreads();
    for (int i = threadIdx.x; i < NPAIR; i += blockDim.x)
        atomicAdd(&cnt[g_ke[i]], 1);
    __syncthreads();
    if (threadIdx.x == 0) {
        int s = 0, ts = 0;
        for (int e = 0; e < E_NUM; e++) {
            off_s[e] = s;
            g_off[e] = s;
            g_toff[e] = ts;
            s += cnt[e];
            ts += (cnt[e] + 127) / 128;
        }
        off_s[E_NUM] = s;
        g_off[E_NUM] = s;
        g_toff[E_NUM] = ts;
    }
    __syncthreads();
    for (int i = threadIdx.x; i < NPAIR; i += blockDim.x) {
        int e = g_ke[i];
        int pos = off_s[e] + atomicAdd(&fill[e], 1);
        g_stok[pos] = i >> 1;
        g_sw[pos] = g_kw[i];
    }
}

// ---------------- 3) gather + fp16 A ----------------
__global__ void gather_x_kernel(const float* __restrict__ x) {
    int row = blockIdx.x * 4 + (threadIdx.x >> 6);
    int grp = threadIdx.x & 63;
    int tok = g_stok[row];
    const float4* s = (const float4*)(x + (size_t)tok * H_DIM + grp * 16);
    float4 v0 = s[0], v1 = s[1], v2 = s[2], v3 = s[3];
    __half o[16];
    o[0]  = __float2half_rn(v0.x); o[1]  = __float2half_rn(v0.y);
    o[2]  = __float2half_rn(v0.z); o[3]  = __float2half_rn(v0.w);
    o[4]  = __float2half_rn(v1.x); o[5]  = __float2half_rn(v1.y);
    o[6]  = __float2half_rn(v1.z); o[7]  = __float2half_rn(v1.w);
    o[8]  = __float2half_rn(v2.x); o[9]  = __float2half_rn(v2.y);
    o[10] = __float2half_rn(v2.z); o[11] = __float2half_rn(v2.w);
    o[12] = __float2half_rn(v3.x); o[13] = __float2half_rn(v3.y);
    o[14] = __float2half_rn(v3.z); o[15] = __float2half_rn(v3.w);
    uint4* d = (uint4*)(g_axh + (size_t)row * H_DIM + grp * 16);
    d[0] = ((const uint4*)o)[0];
    d[1] = ((const uint4*)o)[1];
}

// ---------------- 4) gate+up GEMM (R11 config: BM=128, 3-stage, ldmatrix) ----------------
__global__ __launch_bounds__(256, 2)
void gateup_mm(const __half* __restrict__ gw, const __half* __restrict__ uw)
{
    const int wi = blockIdx.x;
    const int mtile = wi >> 6;
    if (mtile >= g_toff[E_NUM]) return;
    int e = 0;
#pragma unroll
    for (int k = 1; k < E_NUM; k++) if (mtile >= g_toff[k]) e = k;
    const int off0 = g_off[e];
    const int nrows = g_off[e + 1] - off0;
    const int m0 = (mtile - g_toff[e]) * 128;
    const int n0 = (wi & 63) * 64;
    const int tid = threadIdx.x;
    const int wid = tid >> 5, lane = tid & 31;
    const int warpM = wid & 3, warpN = wid >> 2;
    const int g = lane >> 2, t = lane & 3;

    extern __shared__ __half smh[];
    __shared__ float ws[128];
    const uint32_t sbase = smem_u32(smh);

    if (tid < 128) {
        int r = m0 + tid;
        ws[tid] = (r < nrows) ? g_sw[off0 + r] : 0.f;
    }

    const __half* aSrc[4]; uint32_t aDst[4];
#pragma unroll
    for (int i = 0; i < 4; i++) {
        int c = tid + 256 * i;
        int row = c >> 3, col = c & 7;
        int r = m0 + row; if (r > nrows - 1) r = nrows - 1;
        aSrc[i] = g_axh + (size_t)(off0 + r) * H_DIM + col * 8;
        aDst[i] = sbase + (row * PADH + col * 8) * 2;
    }
    const __half* gSrc[2]; const __half* uSrc[2]; uint32_t bDst[2];
#pragma unroll
    for (int i = 0; i < 2; i++) {
        int c = tid + 256 * i;
        int row = c >> 3, col = c & 7;
        gSrc[i] = gw + (size_t)e * F_DIM * H_DIM + (size_t)(n0 + row) * H_DIM + col * 8;
        uSrc[i] = uw + (size_t)e * F_DIM * H_DIM + (size_t)(n0 + row) * H_DIM + col * 8;
        bDst[i] = sbase + (row * PADH + col * 8) * 2;
    }

    uint32_t aoff[2];
#pragma unroll
    for (int mt = 0; mt < 2; mt++)
        aoff[mt] = (uint32_t)(((warpM * 32 + mt * 16 + (lane & 15)) * PADH
                               + ((lane >> 4) & 1) * 8) * 2);
    const int brow = (lane & 7) + ((lane >> 4) & 1) * 8;
    const int bks  = ((lane >> 3) & 1) * 8;
    uint32_t boff[2];
#pragma unroll
    for (int p = 0; p < 2; p++)
        boff[p] = (uint32_t)(((warpN * 32 + p * 16 + brow) * PADH + bks) * 2);

    float accg[2][4][4], accu[2][4][4];
#pragma unroll
    for (int mt = 0; mt < 2; mt++)
#pragma unroll
        for (int nt = 0; nt < 4; nt++)
#pragma unroll
            for (int i = 0; i < 4; i++) { accg[mt][nt][i] = 0.f; accu[mt][nt][i] = 0.f; }

    const int NK = H_DIM / 64;  // 16
#pragma unroll
    for (int pk = 0; pk < 2; pk++) {
        const uint32_t so = (uint32_t)(pk * GU_STGH * 2);
        const int ko = pk * 64;
#pragma unroll
        for (int i = 0; i < 4; i++) cp16(aDst[i] + so, aSrc[i] + ko);
#pragma unroll
        for (int i = 0; i < 2; i++) cp16(bDst[i] + so + GU_BG * 2, gSrc[i] + ko);
#pragma unroll
        for (int i = 0; i < 2; i++) cp16(bDst[i] + so + GU_BU * 2, uSrc[i] + ko);
        CP_COMMIT();
    }

    int s = 0;
    for (int kb = 0; kb < NK; kb++) {
        if (kb + 1 < NK) CP_WAIT1(); else CP_WAIT0();
        __syncthreads();
        if (kb + 2 < NK) {
            const int s2 = (s + 2 >= NSTG) ? (s + 2 - NSTG) : (s + 2);
            const uint32_t so = (uint32_t)(s2 * GU_STGH * 2);
            const int ko = (kb + 2) * 64;
#pragma unroll
            for (int i = 0; i < 4; i++) cp16(aDst[i] + so, aSrc[i] + ko);
#pragma unroll
            for (int i = 0; i < 2; i++) cp16(bDst[i] + so + GU_BG * 2, gSrc[i] + ko);
#pragma unroll
            for (int i = 0; i < 2; i++) cp16(bDst[i] + so + GU_BU * 2, uSrc[i] + ko);
            CP_COMMIT();
        }
        const uint32_t sA = sbase + (uint32_t)(s * GU_STGH * 2);
#pragma unroll
        for (int ks = 0; ks < 4; ks++) {
            const uint32_t kofs = (uint32_t)(ks * 32);
            unsigned a[2][4], bg[2][4], bu[2][4];
#pragma unroll
            for (int mt = 0; mt < 2; mt++)
                ldsm_x4(a[mt][0], a[mt][1], a[mt][2], a[mt][3], sA + aoff[mt] + kofs);
#pragma unroll
            for (int p = 0; p < 2; p++) {
                ldsm_x4(bg[p][0], bg[p][1], bg[p][2], bg[p][3], sA + GU_BG * 2 + boff[p] + kofs);
                ldsm_x4(bu[p][0], bu[p][1], bu[p][2], bu[p][3], sA + GU_BU * 2 + boff[p] + kofs);
            }
#pragma unroll
            for (int mt = 0; mt < 2; mt++)
#pragma unroll
                for (int p = 0; p < 2; p++) {
                    mma_f16(accg[mt][p * 2 + 0], a[mt], &bg[p][0]);
                    mma_f16(accg[mt][p * 2 + 1], a[mt], &bg[p][2]);
                    mma_f16(accu[mt][p * 2 + 0], a[mt], &bu[p][0]);
                    mma_f16(accu[mt][p * 2 + 1], a[mt], &bu[p][2]);
                }
        }
        s = (s + 1 >= NSTG) ? 0 : (s + 1);
    }

    // epilogue: hid = fp16( w * silu(g) * u )
#pragma unroll
    for (int mt = 0; mt < 2; mt++) {
#pragma unroll
        for (int nt = 0; nt < 4; nt++) {
            const int col = n0 + warpN * 32 + nt * 8 + t * 2;
#pragma unroll
            for (int h = 0; h < 2; h++) {
                const int row = warpM * 32 + mt * 16 + g + h * 8;
                if (m0 + row < nrows) {
                    float w  = ws[row];
                    float g0 = accg[mt][nt][h * 2 + 0], g1 = accg[mt][nt][h * 2 + 1];
                    float u0 = accu[mt][nt][h * 2 + 0], u1 = accu[mt][nt][h * 2 + 1];
                    float h0 = w * u0 * (g0 / (1.f + __expf(-g0)));
                    float h1 = w * u1 * (g1 / (1.f + __expf(-g1)));
                    *(__half2*)(g_hidh + (size_t)(off0 + m0 + row) * F_DIM + col) =
                        __floats2half2_rn(h0, h1);
                }
            }
        }
    }
}

// ---------------- 5) down GEMM (R11 config: BM=128, 3-stage, fused combine) ----------------
__global__ __launch_bounds__(256, 2)
void down_mm(float* __restrict__ out)
{
    const int wi = blockIdx.x;
    const int mtile = wi >> 3;
    if (mtile >= g_toff[E_NUM]) return;
    int e = 0;
#pragma unroll
    for (int k = 1; k < E_NUM; k++) if (mtile >= g_toff[k]) e = k;
    const int off0 = g_off[e];
    const int nrows = g_off[e + 1] - off0;
    const int m0 = (mtile - g_toff[e]) * 128;
    const int n0 = (wi & 7) * 128;
    const int tid = threadIdx.x;
    const int wid = tid >> 5, lane = tid & 31;
    const int warpM = wid & 3, warpN = wid >> 2;
    const int g = lane >> 2, t = lane & 3;

    extern __shared__ __half smh[];
    const uint32_t sbase = smem_u32(smh);

    const __half* aSrc[4]; uint32_t aDst[4];
    const __half* bSrc[4]; uint32_t bDst[4];
#pragma unroll
    for (int i = 0; i < 4; i++) {
        int c = tid + 256 * i;
        int row = c >> 3, col = c & 7;
        int r = m0 + row; if (r > nrows - 1) r = nrows - 1;
        aSrc[i] = g_hidh + (size_t)(off0 + r) * F_DIM + col * 8;
        aDst[i] = sbase + (row * PADH + col * 8) * 2;
        bSrc[i] = g_dwh + (size_t)e * H_DIM * F_DIM + (size_t)(n0 + row) * F_DIM + col * 8;
        bDst[i] = sbase + ((DN_BB + row * PADH + col * 8)) * 2;
    }

    uint32_t aoff[2];
#pragma unroll
    for (int mt = 0; mt < 2; mt++)
        aoff[mt] = (uint32_t)(((warpM * 32 + mt * 16 + (lane & 15)) * PADH
                               + ((lane >> 4) & 1) * 8) * 2);
    const int brow = (lane & 7) + ((lane >> 4) & 1) * 8;
    const int bks  = ((lane >> 3) & 1) * 8;
    uint32_t boff[4];
#pragma unroll
    for (int p = 0; p < 4; p++)
        boff[p] = (uint32_t)(((warpN * 64 + p * 16 + brow) * PADH + bks) * 2);

    float acc[2][8][4];
#pragma unroll
    for (int mt = 0; mt < 2; mt++)
#pragma unroll
        for (int nt = 0; nt < 8; nt++)
#pragma unroll
            for (int i = 0; i < 4; i++) acc[mt][nt][i] = 0.f;

    const int NK = F_DIM / 64;  // 64
#pragma unroll
    for (int pk = 0; pk < 2; pk++) {
        const uint32_t so = (uint32_t)(pk * DN_STGH * 2);
        const int ko = pk * 64;
#pragma unroll
        for (int i = 0; i < 4; i++) {
            cp16(aDst[i] + so, aSrc[i] + ko);
            cp16(bDst[i] + so, bSrc[i] + ko);
        }
        CP_COMMIT();
    }

    int s = 0;
    for (int kb = 0; kb < NK; kb++) {
        if (kb + 1 < NK) CP_WAIT1(); else CP_WAIT0();
        __syncthreads();
        if (kb + 2 < NK) {
            const int s2 = (s + 2 >= NSTG) ? (s + 2 - NSTG) : (s + 2);
            const uint32_t so = (uint32_t)(s2 * DN_STGH * 2);
            const int ko = (kb + 2) * 64;
#pragma unroll
            for (int i = 0; i < 4; i++) {
                cp16(aDst[i] + so, aSrc[i] + ko);
                cp16(bDst[i] + so, bSrc[i] + ko);
            }
            CP_COMMIT();
        }
        const uint32_t sA = sbase + (uint32_t)(s * DN_STGH * 2);
#pragma unroll
        for (int ks = 0; ks < 4; ks++) {
            const uint32_t kofs = (uint32_t)(ks * 32);
            unsigned a[2][4], b[4][4];
#pragma unroll
            for (int mt = 0; mt < 2; mt++)
                ldsm_x4(a[mt][0], a[mt][1], a[mt][2], a[mt][3], sA + aoff[mt] + kofs);
#pragma unroll
            for (int p = 0; p < 4; p++)
                ldsm_x4(b[p][0], b[p][1], b[p][2], b[p][3], sA + DN_BB * 2 + boff[p] + kofs);
#pragma unroll
            for (int mt = 0; mt < 2; mt++)
#pragma unroll
                for (int p = 0; p < 4; p++) {
                    mma_f16(acc[mt][p * 2 + 0], a[mt], &b[p][0]);
                    mma_f16(acc[mt][p * 2 + 1], a[mt], &b[p][2]);
                }
        }
        s = (s + 1 >= NSTG) ? 0 : (s + 1);
    }

    // epilogue: atomicAdd into output (exactly 2 contributions per element -> deterministic)
#pragma unroll
    for (int mt = 0; mt < 2; mt++) {
#pragma unroll
        for (int h = 0; h < 2; h++) {
            const int row = warpM * 32 + mt * 16 + g + h * 8;
            if (m0 + row < nrows) {
                const int tok = g_stok[off0 + m0 + row];
                float* po = out + (size_t)tok * H_DIM;
#pragma unroll
                for (int nt = 0; nt < 8; nt++) {
                    const int col = n0 + warpN * 64 + nt * 8 + t * 2;
                    atomicAdd(po + col,     acc[mt][nt][h * 2 + 0]);
                    atomicAdd(po + col + 1, acc[mt][nt][h * 2 + 1]);
                }
            }
        }
    }
}

// ---------------- launch ----------------
extern "C" void kernel_launch(void* const* d_in, const int* in_sizes, int n_in,
                              void* d_out, int out_size) {
    (void)in_sizes; (void)n_in; (void)out_size;
    const float* x  = (const float*)d_in[0];
    const float* rw = (const float*)d_in[1];
    const float* gw = (const float*)d_in[2];
    const float* uw = (const float*)d_in[3];
    const float* dw = (const float*)d_in[4];
    float* out = (float*)d_out;

    cudaFuncSetAttribute(gateup_mm, cudaFuncAttributeMaxDynamicSharedMemorySize, GU_SMEM);
    cudaFuncSetAttribute(down_mm,   cudaFuncAttributeMaxDynamicSharedMemorySize, DN_SMEM);

    __half* gwh; __half* uwh; __half* dwh;
    cudaGetSymbolAddress((void**)&gwh, g_gwh);
    cudaGetSymbolAddress((void**)&uwh, g_uwh);
    cudaGetSymbolAddress((void**)&dwh, g_dwh);

    const int n16 = WEL / 16;

    // launch order: gateup_mm is the 4th launch (= ncu's profiled slot)
    prep_kernel<<<dim3(4096, 5), 256>>>(x, rw, gw, uw, dw, gwh, uwh, dwh, out, n16); // 1 (prep ∥ router)
    build_kernel<<<1, 256>>>();                                                      // 2
    gather_x_kernel<<<NPAIR / 4, 256>>>(x);                                          // 3
    gateup_mm<<<MT_MAX * 64, 256, GU_SMEM>>>(gwh, uwh);                              // 4 <- profiled
    down_mm<<<MT_MAX * 8, 256, DN_SMEM>>>(out);                                      // 5
}